// round 14
// baseline (speedup 1.0000x reference)
#include <cuda_runtime.h>
#include <cuda_fp16.h>

#define B_    8
#define CIN   256
#define COUT  256
#define H_    64
#define W_    64
#define L_    4096
#define K2_   9
#define NCH16 144        // 9 k2 * 16 ci-chunks of 16 (B-bake granularity)
#define NCH   72         // 9 k2 * 8  ci-chunks of 32 (GEMM granularity)

// per buffer: A 4KB (2 subs x 2KB) | B 16KB (2 subs x 8KB)
#define BUF_BYTES 20480

// Scratch (static __device__ arrays — no runtime allocation)
__device__ int4     d_mi[B_ * K2_ * L_];     // bilinear corner indices [b][k2][l]
__device__ float4   d_mw[B_ * K2_ * L_];     // bilinear corner weights (masked)
__device__ unsigned d_Bf[NCH16 * 2048];      // fp16 B frags [chunk16][tile][lane][reg]
__device__ __half   d_xT[(size_t)B_ * L_ * CIN];  // x transposed, fp16 [b][pixel][ci]

// ---------------------------------------------------------------------------
__device__ __forceinline__ void mma_fp16(float* d, const unsigned* a,
                                         const unsigned* b) {
    asm volatile(
        "mma.sync.aligned.m16n8k16.row.col.f32.f16.f16.f32 "
        "{%0,%1,%2,%3}, {%4,%5,%6,%7}, {%8,%9}, {%0,%1,%2,%3};"
        : "+f"(d[0]), "+f"(d[1]), "+f"(d[2]), "+f"(d[3])
        : "r"(a[0]), "r"(a[1]), "r"(a[2]), "r"(a[3]), "r"(b[0]), "r"(b[1]));
}
__device__ __forceinline__ void cp16(unsigned dst, const void* src) {
    asm volatile("cp.async.cg.shared.global [%0], [%1], 16;"
                 :: "r"(dst), "l"(src));
}
#define CP_COMMIT() asm volatile("cp.async.commit_group;" ::: "memory")
#define CP_WAIT0()  asm volatile("cp.async.wait_group 0;" ::: "memory")

__device__ __forceinline__ unsigned pack16(float v0, float v1) {
    __half2 h = __floats2half2_rn(v0, v1);
    return *(unsigned*)&h;
}

// weighted bilinear blend of 4 fp16 corner octets -> 4 packed fp16x2 words
__device__ __forceinline__ void blend4(const uint4& g0, const uint4& g1,
                                       const uint4& g2, const uint4& g3,
                                       float4 w, unsigned* o) {
    const __half2* h0 = (const __half2*)&g0;
    const __half2* h1 = (const __half2*)&g1;
    const __half2* h2 = (const __half2*)&g2;
    const __half2* h3 = (const __half2*)&g3;
#pragma unroll
    for (int j = 0; j < 4; ++j) {
        float2 f0 = __half22float2(h0[j]);
        float2 f1 = __half22float2(h1[j]);
        float2 f2 = __half22float2(h2[j]);
        float2 f3 = __half22float2(h3[j]);
        o[j] = pack16(w.x * f0.x + w.y * f1.x + w.z * f2.x + w.w * f3.x,
                      w.x * f0.y + w.y * f1.y + w.z * f2.y + w.w * f3.y);
    }
}

// ---------------------------------------------------------------------------
// Kernel 0: transpose x NCHW -> NHWC fp16 ([b][ci][l] -> [b][l][ci])
// ---------------------------------------------------------------------------
__global__ void tr_kernel(const float* __restrict__ x) {
    __shared__ float t[32][33];
    const int tx = threadIdx.x & 31, ty = threadIdx.x >> 5;
    const int l0 = blockIdx.x << 5;
    const int c0 = blockIdx.y << 5;
    const int b  = blockIdx.z;
    const float* xb = x + ((size_t)b * CIN + c0) * L_ + l0;
#pragma unroll
    for (int i = 0; i < 4; ++i)
        t[ty + i * 8][tx] = xb[(size_t)(ty + i * 8) * L_ + tx];
    __syncthreads();
    __half* ob = d_xT + ((size_t)b * L_ + l0) * CIN + c0;
#pragma unroll
    for (int i = 0; i < 4; ++i)
        ob[(size_t)(ty + i * 8) * CIN + tx] = __float2half_rn(t[tx][ty + i * 8]);
}

// ---------------------------------------------------------------------------
// Kernel 1: bilinear metadata (validated)
// ---------------------------------------------------------------------------
__global__ void meta_kernel(const float* __restrict__ anc) {
    int g = blockIdx.x * blockDim.x + threadIdx.x;
    if (g >= B_ * K2_ * L_) return;
    int l = g % L_, k2 = (g / L_) % K2_, b = g / (L_ * K2_);

    const float* a = anc + (size_t)(b * L_ + l) * 5;
    float xc = a[0] * 0.125f, yc = a[1] * 0.125f;
    float dw = (a[2] * 0.125f) / 3.0f, dh = (a[3] * 0.125f) / 3.0f;
    float s, c;
    sincosf(a[4], &s, &c);
    float fx = (float)(k2 % 3) - 1.0f, fy = (float)(k2 / 3) - 1.0f;
    float xk = dw * fx, yk = dh * fy;
    float px = (c * xk - s * yk) + xc;
    float py = (s * xk + c * yk) + yc;

    float x0f = floorf(px), y0f = floorf(py);
    int x0 = (int)x0f, y0 = (int)y0f;
    float wx1 = px - x0f, wy1 = py - y0f;
    float wx0 = 1.0f - wx1, wy0 = 1.0f - wy1;
    int x1 = x0 + 1, y1 = y0 + 1;
    float vx0 = (x0 >= 0 && x0 < W_) ? 1.f : 0.f;
    float vx1 = (x1 >= 0 && x1 < W_) ? 1.f : 0.f;
    float vy0 = (y0 >= 0 && y0 < H_) ? 1.f : 0.f;
    float vy1 = (y1 >= 0 && y1 < H_) ? 1.f : 0.f;
    int xc0 = min(max(x0, 0), W_ - 1), xc1 = min(max(x1, 0), W_ - 1);
    int yc0 = min(max(y0, 0), H_ - 1), yc1 = min(max(y1, 0), H_ - 1);
    d_mi[g] = make_int4(yc0 * W_ + xc0, yc0 * W_ + xc1,
                        yc1 * W_ + xc0, yc1 * W_ + xc1);
    d_mw[g] = make_float4(wy0 * wx0 * vy0 * vx0, wy0 * wx1 * vy0 * vx1,
                          wy1 * wx0 * vy1 * vx0, wy1 * wx1 * vy1 * vx1);
}

// ---------------------------------------------------------------------------
// Kernel 2: bake B into mma fragment order, single fp16 matrix (validated).
// ---------------------------------------------------------------------------
__global__ void bf_kernel(const float* __restrict__ w) {
    int i = blockIdx.x * blockDim.x + threadIdx.x;
    if (i >= NCH16 * 2048) return;
    int chunk = i >> 11;
    int r2    = i & 2047;
    int tile  = r2 >> 6;
    int lane  = (r2 >> 1) & 31;
    int reg   = r2 & 1;

    int co = tile * 8 + (lane >> 2);
    int kb = 2 * (lane & 3) + 8 * reg;
    int ci = (chunk & 15) * 16 + kb;
    int k2 = chunk >> 4;

    float v0 = w[((size_t)co * CIN + ci) * K2_ + k2];
    float v1 = w[((size_t)co * CIN + ci + 1) * K2_ + k2];
    d_Bf[i] = pack16(v0, v1);
}

// ---------------------------------------------------------------------------
// Kernel 3: implicit GEMM, mma.sync fp16, 32-ci chunks, fp16 JIT gather.
//   CTA: M=64 px x N=256 couts, 256 threads (8 warps: 2M x 4N, warp 32x64).
//   3 CTAs/SM (launch_bounds regs<=84): occupancy is the lever this round.
//   Thread (q=tid&3 -> 8-ci octet, pxl=tid>>2) gathers one pixel per chunk.
// ---------------------------------------------------------------------------
__global__ __launch_bounds__(256, 3)
void gemm_kernel(float* __restrict__ out) {
    __shared__ uint4 smem4[2 * BUF_BYTES / 16];   // 40 KB static
    char* smem = (char*)smem4;
    const unsigned smem_b = (unsigned)__cvta_generic_to_shared(smem);

    const int tid  = threadIdx.x;
    const int lane = tid & 31;
    const int wid  = tid >> 5;
    const int b    = blockIdx.x >> 6;
    const int l0   = (blockIdx.x & 63) << 6;   // 64-pixel tiles
    const int q    = tid & 3;                  // 8-ci octet within 32-chunk
    const int pxl  = tid >> 2;                 // pixel (0..63)

    // --- producer A STS addressing (validated granule layout) ---
    const int r   = pxl & 15, mt = pxl >> 4;   // mt 0..3
    const int rs  = (r >> 1) & 3;
    const int sabase  = (mt * 32 + ((r & 7) << 2)) * 16
                      + (2 * (q & 1) + (r >= 8)) * 4;
    const int subbase = (q >> 1) * 2048;       // 16-ci sub-chunk region

    // --- consumer fragment bases (validated R9) ---
    const int ca0 = (wid & 1) * 1024 + (lane ^ ((lane >> 3) & 3)) * 16;
    const int bo0 = (wid >> 1) * 2048 + lane * 8;

    float acc[2][8][4];
#pragma unroll
    for (int i = 0; i < 2; ++i)
#pragma unroll
        for (int t = 0; t < 8; ++t)
#pragma unroll
            for (int w0 = 0; w0 < 4; ++w0) acc[i][t][w0] = 0.0f;

    const __half* xTb = d_xT + (size_t)b * L_ * CIN;
    int4 mi4; float4 mw4;
    {
        int mx = (b * K2_) * L_ + l0 + pxl;
        mi4 = d_mi[mx]; mw4 = d_mw[mx];
    }

    // ---- prologue: chunk 0 -> buffer 0 ----
    {
#pragma unroll
        for (int i = 0; i < 4; ++i)
            cp16(smem_b + 4096 + (tid + i * 256) * 16,
                 d_Bf + (tid + i * 256) * 4);
        CP_COMMIT();

        const __half* basep = xTb + 8 * q;
        uint4 g0 = __ldg((const uint4*)(basep + (size_t)mi4.x * 256));
        uint4 g1 = __ldg((const uint4*)(basep + (size_t)mi4.y * 256));
        uint4 g2 = __ldg((const uint4*)(basep + (size_t)mi4.z * 256));
        uint4 g3 = __ldg((const uint4*)(basep + (size_t)mi4.w * 256));
        unsigned o[4];
        blend4(g0, g1, g2, g3, mw4, o);
        char* An = smem + subbase;
#pragma unroll
        for (int j = 0; j < 4; ++j)
            *(unsigned*)(An + sabase + ((j ^ rs) << 4)) = o[j];
        CP_WAIT0();
    }
    __syncthreads();

    for (int ch = 0; ch < NCH; ++ch) {
        const int base  = (ch & 1) * BUF_BYTES;
        const int nbase = ((ch & 1) ^ 1) * BUF_BYTES;
        const bool more = (ch + 1) < NCH;
        const int nc = ch + 1;

        if (more) {
            if ((nc & 7) == 0) {      // k2 advances every 8 chunks
                int mx = (b * K2_ + (nc >> 3)) * L_ + l0 + pxl;
                mi4 = d_mi[mx]; mw4 = d_mw[mx];
            }
            const unsigned dstB = smem_b + nbase + 4096;
            const unsigned* srcB = d_Bf + nc * 4096;
#pragma unroll
            for (int i = 0; i < 4; ++i)
                cp16(dstB + (tid + i * 256) * 16, srcB + (tid + i * 256) * 4);
            CP_COMMIT();
        }

        // ---- math: 2 x 16-ci subs (validated R9 datapath) ----
        {
            char* Ab = smem + base;
#pragma unroll
            for (int s = 0; s < 2; ++s) {
                const char* Ar = Ab + s * 2048;
                const char* Br = Ab + 4096 + s * 8192;
                uint4 ah0 = *(const uint4*)(Ar + ca0);
                uint4 ah1 = *(const uint4*)(Ar + ca0 + 512);
                uint2 bfr[8];
#pragma unroll
                for (int t = 0; t < 8; ++t)
                    bfr[t] = *(const uint2*)(Br + bo0 + t * 256);
#pragma unroll
                for (int t = 0; t < 8; ++t) {
                    mma_fp16(acc[0][t], (const unsigned*)&ah0,
                             (const unsigned*)&bfr[t]);
                    mma_fp16(acc[1][t], (const unsigned*)&ah1,
                             (const unsigned*)&bfr[t]);
                }
            }
        }

        if (more) {
            // JIT gather of chunk nc (overlap comes from co-resident CTAs)
            const __half* basep = xTb + (nc & 7) * 32 + 8 * q;
            uint4 g0 = __ldg((const uint4*)(basep + (size_t)mi4.x * 256));
            uint4 g1 = __ldg((const uint4*)(basep + (size_t)mi4.y * 256));
            uint4 g2 = __ldg((const uint4*)(basep + (size_t)mi4.z * 256));
            uint4 g3 = __ldg((const uint4*)(basep + (size_t)mi4.w * 256));
            unsigned o[4];
            blend4(g0, g1, g2, g3, mw4, o);
            char* An = smem + nbase + subbase;
#pragma unroll
            for (int j = 0; j < 4; ++j)
                *(unsigned*)(An + sabase + ((j ^ rs) << 4)) = o[j];
        }
        CP_WAIT0();
        __syncthreads();
    }

    // ---- epilogue: relu + direct stores (validated R9) ----
    const int ncol = wid >> 1;
#pragma unroll
    for (int i = 0; i < 2; ++i) {
        int pxg = l0 + ((wid & 1) * 2 + i) * 16 + (lane >> 2);
#pragma unroll
        for (int t = 0; t < 8; ++t) {
            int co = ncol * 64 + t * 8 + 2 * (lane & 3);
            float* o0 = out + ((size_t)(b * COUT + co)) * L_ + pxg;
            float* o1 = o0 + L_;
            o0[0] = fmaxf(acc[i][t][0], 0.0f);
            o1[0] = fmaxf(acc[i][t][1], 0.0f);
            o0[8] = fmaxf(acc[i][t][2], 0.0f);
            o1[8] = fmaxf(acc[i][t][3], 0.0f);
        }
    }
}

// ---------------------------------------------------------------------------
extern "C" void kernel_launch(void* const* d_in, const int* in_sizes, int n_in,
                              void* d_out, int out_size) {
    const float* x   = (const float*)d_in[0];  // [8,256,64,64]
    const float* anc = (const float*)d_in[1];  // [8,4096,5]
    const float* w   = (const float*)d_in[2];  // [256,256,3,3]
    float* out = (float*)d_out;                // [8,256,64,64]

    tr_kernel<<<dim3(128, 8, 8), 256>>>(x);
    meta_kernel<<<(B_ * K2_ * L_ + 255) / 256, 256>>>(anc);
    bf_kernel<<<(NCH16 * 2048 + 255) / 256, 256>>>(w);
    gemm_kernel<<<512, 256>>>(out);
}

// round 15
// speedup vs baseline: 1.1522x; 1.1522x over previous
#include <cuda_runtime.h>
#include <cuda_fp16.h>

#define B_    8
#define CIN   256
#define COUT  256
#define H_    64
#define W_    64
#define L_    4096
#define K2_   9
#define NCH16 144        // 9 k2 * 16 ci-chunks of 16 (B-bake granularity)
#define NCH   72         // 9 k2 * 8  ci-chunks of 32 (GEMM granularity)

// per buffer: A 4KB (2 subs x 2KB) | B 16KB (2 subs x 8KB)
#define BUF_BYTES 20480

// Scratch (static __device__ arrays — no runtime allocation)
__device__ int4     d_mi[B_ * K2_ * L_];     // bilinear corner indices [b][k2][l]
__device__ float4   d_mw[B_ * K2_ * L_];     // bilinear corner weights (masked)
__device__ unsigned d_Bf[NCH16 * 2048];      // fp16 B frags [chunk16][tile][lane][reg]
__device__ __half   d_xT[(size_t)B_ * L_ * CIN];  // x transposed, fp16 [b][pixel][ci]

// ---------------------------------------------------------------------------
__device__ __forceinline__ void mma_fp16(float* d, const unsigned* a,
                                         const unsigned* b) {
    asm volatile(
        "mma.sync.aligned.m16n8k16.row.col.f32.f16.f16.f32 "
        "{%0,%1,%2,%3}, {%4,%5,%6,%7}, {%8,%9}, {%0,%1,%2,%3};"
        : "+f"(d[0]), "+f"(d[1]), "+f"(d[2]), "+f"(d[3])
        : "r"(a[0]), "r"(a[1]), "r"(a[2]), "r"(a[3]), "r"(b[0]), "r"(b[1]));
}
__device__ __forceinline__ void cp16(unsigned dst, const void* src) {
    asm volatile("cp.async.cg.shared.global [%0], [%1], 16;"
                 :: "r"(dst), "l"(src));
}
#define CP_COMMIT() asm volatile("cp.async.commit_group;" ::: "memory")
#define CP_WAIT0()  asm volatile("cp.async.wait_group 0;" ::: "memory")

__device__ __forceinline__ unsigned pack16(float v0, float v1) {
    __half2 h = __floats2half2_rn(v0, v1);
    return *(unsigned*)&h;
}

// weighted bilinear blend of 4 fp16 corner octets -> 4 packed fp16x2 words
__device__ __forceinline__ void blend4(const uint4& g0, const uint4& g1,
                                       const uint4& g2, const uint4& g3,
                                       float4 w, unsigned* o) {
    const __half2* h0 = (const __half2*)&g0;
    const __half2* h1 = (const __half2*)&g1;
    const __half2* h2 = (const __half2*)&g2;
    const __half2* h3 = (const __half2*)&g3;
#pragma unroll
    for (int j = 0; j < 4; ++j) {
        float2 f0 = __half22float2(h0[j]);
        float2 f1 = __half22float2(h1[j]);
        float2 f2 = __half22float2(h2[j]);
        float2 f3 = __half22float2(h3[j]);
        o[j] = pack16(w.x * f0.x + w.y * f1.x + w.z * f2.x + w.w * f3.x,
                      w.x * f0.y + w.y * f1.y + w.z * f2.y + w.w * f3.y);
    }
}

// ---------------------------------------------------------------------------
// Kernel 0: transpose x NCHW -> NHWC fp16 ([b][ci][l] -> [b][l][ci])
// ---------------------------------------------------------------------------
__global__ void tr_kernel(const float* __restrict__ x) {
    __shared__ float t[32][33];
    const int tx = threadIdx.x & 31, ty = threadIdx.x >> 5;
    const int l0 = blockIdx.x << 5;
    const int c0 = blockIdx.y << 5;
    const int b  = blockIdx.z;
    const float* xb = x + ((size_t)b * CIN + c0) * L_ + l0;
#pragma unroll
    for (int i = 0; i < 4; ++i)
        t[ty + i * 8][tx] = xb[(size_t)(ty + i * 8) * L_ + tx];
    __syncthreads();
    __half* ob = d_xT + ((size_t)b * L_ + l0) * CIN + c0;
#pragma unroll
    for (int i = 0; i < 4; ++i)
        ob[(size_t)(ty + i * 8) * CIN + tx] = __float2half_rn(t[tx][ty + i * 8]);
}

// ---------------------------------------------------------------------------
// Kernel 1: bilinear metadata (validated)
// ---------------------------------------------------------------------------
__global__ void meta_kernel(const float* __restrict__ anc) {
    int g = blockIdx.x * blockDim.x + threadIdx.x;
    if (g >= B_ * K2_ * L_) return;
    int l = g % L_, k2 = (g / L_) % K2_, b = g / (L_ * K2_);

    const float* a = anc + (size_t)(b * L_ + l) * 5;
    float xc = a[0] * 0.125f, yc = a[1] * 0.125f;
    float dw = (a[2] * 0.125f) / 3.0f, dh = (a[3] * 0.125f) / 3.0f;
    float s, c;
    sincosf(a[4], &s, &c);
    float fx = (float)(k2 % 3) - 1.0f, fy = (float)(k2 / 3) - 1.0f;
    float xk = dw * fx, yk = dh * fy;
    float px = (c * xk - s * yk) + xc;
    float py = (s * xk + c * yk) + yc;

    float x0f = floorf(px), y0f = floorf(py);
    int x0 = (int)x0f, y0 = (int)y0f;
    float wx1 = px - x0f, wy1 = py - y0f;
    float wx0 = 1.0f - wx1, wy0 = 1.0f - wy1;
    int x1 = x0 + 1, y1 = y0 + 1;
    float vx0 = (x0 >= 0 && x0 < W_) ? 1.f : 0.f;
    float vx1 = (x1 >= 0 && x1 < W_) ? 1.f : 0.f;
    float vy0 = (y0 >= 0 && y0 < H_) ? 1.f : 0.f;
    float vy1 = (y1 >= 0 && y1 < H_) ? 1.f : 0.f;
    int xc0 = min(max(x0, 0), W_ - 1), xc1 = min(max(x1, 0), W_ - 1);
    int yc0 = min(max(y0, 0), H_ - 1), yc1 = min(max(y1, 0), H_ - 1);
    d_mi[g] = make_int4(yc0 * W_ + xc0, yc0 * W_ + xc1,
                        yc1 * W_ + xc0, yc1 * W_ + xc1);
    d_mw[g] = make_float4(wy0 * wx0 * vy0 * vx0, wy0 * wx1 * vy0 * vx1,
                          wy1 * wx0 * vy1 * vx0, wy1 * wx1 * vy1 * vx1);
}

// ---------------------------------------------------------------------------
// Kernel 2: bake B into mma fragment order, single fp16 matrix (validated).
// ---------------------------------------------------------------------------
__global__ void bf_kernel(const float* __restrict__ w) {
    int i = blockIdx.x * blockDim.x + threadIdx.x;
    if (i >= NCH16 * 2048) return;
    int chunk = i >> 11;
    int r2    = i & 2047;
    int tile  = r2 >> 6;
    int lane  = (r2 >> 1) & 31;
    int reg   = r2 & 1;

    int co = tile * 8 + (lane >> 2);
    int kb = 2 * (lane & 3) + 8 * reg;
    int ci = (chunk & 15) * 16 + kb;
    int k2 = chunk >> 4;

    float v0 = w[((size_t)co * CIN + ci) * K2_ + k2];
    float v1 = w[((size_t)co * CIN + ci + 1) * K2_ + k2];
    d_Bf[i] = pack16(v0, v1);
}

// ---------------------------------------------------------------------------
// Kernel 3: warp-specialized implicit GEMM, mma.sync fp16, 32-ci chunks.
//   CTA: M=64 px x N=256 couts, 384 threads.
//   Warps 0-7:  consumers — pure LDS+MMA (R9-validated datapath), acc=64.
//   Warps 8-11: producers — bilinear gather (fp16), blend, STS, B cp.async.
//   Double-buffered; one __syncthreads per chunk.
// ---------------------------------------------------------------------------
__global__ __launch_bounds__(384)
void gemm_kernel(float* __restrict__ out) {
    __shared__ uint4 smem4[2 * BUF_BYTES / 16];   // 40 KB static
    char* smem = (char*)smem4;
    const unsigned smem_b = (unsigned)__cvta_generic_to_shared(smem);

    const int tid  = threadIdx.x;
    const int lane = tid & 31;
    const int wid  = tid >> 5;
    const int b    = blockIdx.x >> 6;
    const int l0   = (blockIdx.x & 63) << 6;   // 64-pixel tiles
    const bool consumer = (wid < 8);

    // ===== consumer state (R9-validated) =====
    const int ca0 = (wid & 1) * 1024 + (lane ^ ((lane >> 3) & 3)) * 16;
    const int bo0 = ((wid >> 1) & 3) * 2048 + lane * 8;
    float acc[2][8][4];
#pragma unroll
    for (int i = 0; i < 2; ++i)
#pragma unroll
        for (int t = 0; t < 8; ++t)
#pragma unroll
            for (int w0 = 0; w0 < 4; ++w0) acc[i][t][w0] = 0.0f;

    // ===== producer state (R14-validated STS formulas) =====
    const int ptid = tid - 256;                // 0..127 (valid when !consumer)
    const int pxl  = (ptid & 127) >> 1;        // pixel 0..63
    const int h    = ptid & 1;                 // 16-ci half of 32-chunk
    const int r    = pxl & 15, mt = pxl >> 4;
    const int rs   = (r >> 1) & 3;
    const int sa_e = (mt * 32 + ((r & 7) << 2)) * 16 + (r >= 8) * 4; // octet 2h
    const int sa_o = sa_e + 8;                                        // octet 2h+1
    const int sub  = h * 2048;

    const __half* xTb = d_xT + (size_t)b * L_ * CIN;
    int4 mi4; float4 mw4;
    if (!consumer) {
        int mx = (b * K2_) * L_ + l0 + pxl;
        mi4 = d_mi[mx]; mw4 = d_mw[mx];
    }

    // producer: gather + blend + STS one chunk into buffer byte-base `bb`
#define PRODUCE_A(nc, bb) do {                                                \
        const __half* basep = xTb + ((nc) & 7) * 32 + h * 16;                 \
        const uint4* p0 = (const uint4*)(basep + (size_t)mi4.x * 256);        \
        const uint4* p1 = (const uint4*)(basep + (size_t)mi4.y * 256);        \
        const uint4* p2 = (const uint4*)(basep + (size_t)mi4.z * 256);        \
        const uint4* p3 = (const uint4*)(basep + (size_t)mi4.w * 256);        \
        uint4 x0 = __ldg(p0), x1 = __ldg(p0 + 1);                             \
        uint4 y0 = __ldg(p1), y1 = __ldg(p1 + 1);                             \
        uint4 z0 = __ldg(p2), z1 = __ldg(p2 + 1);                             \
        uint4 w0_ = __ldg(p3), w1 = __ldg(p3 + 1);                            \
        unsigned oe[4], oo[4];                                                \
        blend4(x0, y0, z0, w0_, mw4, oe);                                     \
        blend4(x1, y1, z1, w1, mw4, oo);                                      \
        char* An = smem + (bb) + sub;                                         \
        _Pragma("unroll")                                                     \
        for (int j = 0; j < 4; ++j) {                                         \
            *(unsigned*)(An + sa_e + ((j ^ rs) << 4)) = oe[j];                \
            *(unsigned*)(An + sa_o + ((j ^ rs) << 4)) = oo[j];                \
        }                                                                     \
    } while (0)

    // ---- prologue: producers fill buffer 0 with chunk 0 ----
    if (!consumer) {
#pragma unroll
        for (int i = 0; i < 8; ++i)
            cp16(smem_b + 4096 + (ptid + i * 128) * 16,
                 d_Bf + (ptid + i * 128) * 4);
        CP_COMMIT();
        PRODUCE_A(0, 0);
        CP_WAIT0();
    }
    __syncthreads();

    for (int ch = 0; ch < NCH; ++ch) {
        const int base  = (ch & 1) * BUF_BYTES;
        const int nbase = ((ch & 1) ^ 1) * BUF_BYTES;
        const bool more = (ch + 1) < NCH;

        if (consumer) {
            // ---- math: 2 x 16-ci subs (validated R9 datapath) ----
            char* Ab = smem + base;
#pragma unroll
            for (int s = 0; s < 2; ++s) {
                const char* Ar = Ab + s * 2048;
                const char* Br = Ab + 4096 + s * 8192;
                uint4 ah0 = *(const uint4*)(Ar + ca0);
                uint4 ah1 = *(const uint4*)(Ar + ca0 + 512);
                uint2 bfr[8];
#pragma unroll
                for (int t = 0; t < 8; ++t)
                    bfr[t] = *(const uint2*)(Br + bo0 + t * 256);
#pragma unroll
                for (int t = 0; t < 8; ++t) {
                    mma_fp16(acc[0][t], (const unsigned*)&ah0,
                             (const unsigned*)&bfr[t]);
                    mma_fp16(acc[1][t], (const unsigned*)&ah1,
                             (const unsigned*)&bfr[t]);
                }
            }
        } else if (more) {
            const int nc = ch + 1;
            const unsigned dstB = smem_b + nbase + 4096;
            const unsigned* srcB = d_Bf + nc * 4096;
#pragma unroll
            for (int i = 0; i < 8; ++i)
                cp16(dstB + (ptid + i * 128) * 16, srcB + (ptid + i * 128) * 4);
            CP_COMMIT();
            if ((nc & 7) == 0) {      // k2 advances every 8 chunks
                int mx = (b * K2_ + (nc >> 3)) * L_ + l0 + pxl;
                mi4 = d_mi[mx]; mw4 = d_mw[mx];
            }
            PRODUCE_A(nc, nbase);
            CP_WAIT0();
        }
        __syncthreads();
    }

    // ---- epilogue: consumers only — relu + direct stores (validated R9) ----
    if (consumer) {
        const int ncol = (wid >> 1) & 3;
#pragma unroll
        for (int i = 0; i < 2; ++i) {
            int pxg = l0 + ((wid & 1) * 2 + i) * 16 + (lane >> 2);
#pragma unroll
            for (int t = 0; t < 8; ++t) {
                int co = ncol * 64 + t * 8 + 2 * (lane & 3);
                float* o0 = out + ((size_t)(b * COUT + co)) * L_ + pxg;
                float* o1 = o0 + L_;
                o0[0] = fmaxf(acc[i][t][0], 0.0f);
                o1[0] = fmaxf(acc[i][t][1], 0.0f);
                o0[8] = fmaxf(acc[i][t][2], 0.0f);
                o1[8] = fmaxf(acc[i][t][3], 0.0f);
            }
        }
    }
}

// ---------------------------------------------------------------------------
extern "C" void kernel_launch(void* const* d_in, const int* in_sizes, int n_in,
                              void* d_out, int out_size) {
    const float* x   = (const float*)d_in[0];  // [8,256,64,64]
    const float* anc = (const float*)d_in[1];  // [8,4096,5]
    const float* w   = (const float*)d_in[2];  // [256,256,3,3]
    float* out = (float*)d_out;                // [8,256,64,64]

    tr_kernel<<<dim3(128, 8, 8), 256>>>(x);
    meta_kernel<<<(B_ * K2_ * L_ + 255) / 256, 256>>>(anc);
    bf_kernel<<<(NCH16 * 2048 + 255) / 256, 256>>>(w);
    gemm_kernel<<<512, 384>>>(out);
}

// round 16
// speedup vs baseline: 1.4260x; 1.2377x over previous
#include <cuda_runtime.h>
#include <cuda_fp16.h>

#define B_    8
#define CIN   256
#define COUT  256
#define H_    64
#define W_    64
#define L_    4096
#define K2_   9
#define NCH16 144        // 9 k2 * 16 ci-chunks of 16 (B-bake granularity)
#define NCH   36         // 9 k2 * 4  ci-chunks of 64 (GEMM granularity)

#define ABUF  16512      // A region: 4 subs * 4112 (+pad)
#define BUF_BYTES (ABUF + 32768)
#define SMEM_BYTES (2 * BUF_BYTES)

// prep kernel block ranges
#define TR_BLOCKS   8192          // 128 l-tiles * 8 ci-tiles * 8 batches
#define META_BLOCKS 1152          // 294912 / 256
#define BF_BLOCKS   1152          // NCH16*2048 / 256

// Scratch (static __device__ arrays — no runtime allocation)
__device__ int4     d_mi[B_ * K2_ * L_];     // bilinear corner indices [b][k2][l]
__device__ float4   d_mw[B_ * K2_ * L_];     // bilinear corner weights (masked)
__device__ unsigned d_Bf[NCH16 * 2048];      // fp16 B frags [chunk16][tile][lane][reg]
__device__ __half   d_xT[(size_t)B_ * L_ * CIN];  // x transposed, fp16 [b][pixel][ci]

// ---------------------------------------------------------------------------
__device__ __forceinline__ void mma_fp16(float* d, const unsigned* a,
                                         const unsigned* b) {
    asm volatile(
        "mma.sync.aligned.m16n8k16.row.col.f32.f16.f16.f32 "
        "{%0,%1,%2,%3}, {%4,%5,%6,%7}, {%8,%9}, {%0,%1,%2,%3};"
        : "+f"(d[0]), "+f"(d[1]), "+f"(d[2]), "+f"(d[3])
        : "r"(a[0]), "r"(a[1]), "r"(a[2]), "r"(a[3]), "r"(b[0]), "r"(b[1]));
}
__device__ __forceinline__ void cp16(unsigned dst, const void* src) {
    asm volatile("cp.async.cg.shared.global [%0], [%1], 16;"
                 :: "r"(dst), "l"(src));
}
#define CP_COMMIT() asm volatile("cp.async.commit_group;" ::: "memory")
#define CP_WAIT0()  asm volatile("cp.async.wait_group 0;" ::: "memory")

__device__ __forceinline__ unsigned pack16(float v0, float v1) {
    __half2 h = __floats2half2_rn(v0, v1);
    return *(unsigned*)&h;
}

// weighted bilinear blend of 4 fp16 corner octets -> 4 packed fp16x2 words
__device__ __forceinline__ void blend4(const uint4& g0, const uint4& g1,
                                       const uint4& g2, const uint4& g3,
                                       float4 w, unsigned* o) {
    const __half2* h0 = (const __half2*)&g0;
    const __half2* h1 = (const __half2*)&g1;
    const __half2* h2 = (const __half2*)&g2;
    const __half2* h3 = (const __half2*)&g3;
#pragma unroll
    for (int j = 0; j < 4; ++j) {
        float2 f0 = __half22float2(h0[j]);
        float2 f1 = __half22float2(h1[j]);
        float2 f2 = __half22float2(h2[j]);
        float2 f3 = __half22float2(h3[j]);
        o[j] = pack16(w.x * f0.x + w.y * f1.x + w.z * f2.x + w.w * f3.x,
                      w.x * f0.y + w.y * f1.y + w.z * f2.y + w.w * f3.y);
    }
}

// ---------------------------------------------------------------------------
// Fused prep kernel: transpose (fp16 NHWC) | bilinear metadata | B-fragment
// bake, dispatched by block range so the three independent parts overlap.
// ---------------------------------------------------------------------------
__global__ void prep_kernel(const float* __restrict__ x,
                            const float* __restrict__ anc,
                            const float* __restrict__ w) {
    __shared__ float t[32][33];
    const int bx = blockIdx.x;

    if (bx < TR_BLOCKS) {
        // ---- transpose x NCHW -> NHWC fp16 (validated R13) ----
        const int tx = threadIdx.x & 31, ty = threadIdx.x >> 5;
        const int l0 = (bx & 127) << 5;
        const int c0 = ((bx >> 7) & 7) << 5;
        const int b  = bx >> 10;
        const float* xb = x + ((size_t)b * CIN + c0) * L_ + l0;
#pragma unroll
        for (int i = 0; i < 4; ++i)
            t[ty + i * 8][tx] = xb[(size_t)(ty + i * 8) * L_ + tx];
        __syncthreads();
        __half* ob = d_xT + ((size_t)b * L_ + l0) * CIN + c0;
#pragma unroll
        for (int i = 0; i < 4; ++i)
            ob[(size_t)(ty + i * 8) * CIN + tx] =
                __float2half_rn(t[tx][ty + i * 8]);
        return;
    }

    if (bx < TR_BLOCKS + META_BLOCKS) {
        // ---- bilinear metadata (validated) ----
        int g = (bx - TR_BLOCKS) * 256 + threadIdx.x;
        if (g >= B_ * K2_ * L_) return;
        int l = g % L_, k2 = (g / L_) % K2_, b = g / (L_ * K2_);

        const float* a = anc + (size_t)(b * L_ + l) * 5;
        float xc = a[0] * 0.125f, yc = a[1] * 0.125f;
        float dw = (a[2] * 0.125f) / 3.0f, dh = (a[3] * 0.125f) / 3.0f;
        float s, c;
        sincosf(a[4], &s, &c);
        float fx = (float)(k2 % 3) - 1.0f, fy = (float)(k2 / 3) - 1.0f;
        float xk = dw * fx, yk = dh * fy;
        float px = (c * xk - s * yk) + xc;
        float py = (s * xk + c * yk) + yc;

        float x0f = floorf(px), y0f = floorf(py);
        int x0 = (int)x0f, y0 = (int)y0f;
        float wx1 = px - x0f, wy1 = py - y0f;
        float wx0 = 1.0f - wx1, wy0 = 1.0f - wy1;
        int x1 = x0 + 1, y1 = y0 + 1;
        float vx0 = (x0 >= 0 && x0 < W_) ? 1.f : 0.f;
        float vx1 = (x1 >= 0 && x1 < W_) ? 1.f : 0.f;
        float vy0 = (y0 >= 0 && y0 < H_) ? 1.f : 0.f;
        float vy1 = (y1 >= 0 && y1 < H_) ? 1.f : 0.f;
        int xc0 = min(max(x0, 0), W_ - 1), xc1 = min(max(x1, 0), W_ - 1);
        int yc0 = min(max(y0, 0), H_ - 1), yc1 = min(max(y1, 0), H_ - 1);
        d_mi[g] = make_int4(yc0 * W_ + xc0, yc0 * W_ + xc1,
                            yc1 * W_ + xc0, yc1 * W_ + xc1);
        d_mw[g] = make_float4(wy0 * wx0 * vy0 * vx0, wy0 * wx1 * vy0 * vx1,
                              wy1 * wx0 * vy1 * vx0, wy1 * wx1 * vy1 * vx1);
        return;
    }

    // ---- bake B into mma fragment order (validated) ----
    {
        int i = (bx - TR_BLOCKS - META_BLOCKS) * 256 + threadIdx.x;
        if (i >= NCH16 * 2048) return;
        int chunk = i >> 11;
        int r2    = i & 2047;
        int tile  = r2 >> 6;
        int lane  = (r2 >> 1) & 31;
        int reg   = r2 & 1;

        int co = tile * 8 + (lane >> 2);
        int kb = 2 * (lane & 3) + 8 * reg;
        int ci = (chunk & 15) * 16 + kb;
        int k2 = chunk >> 4;

        float v0 = w[((size_t)co * CIN + ci) * K2_ + k2];
        float v1 = w[((size_t)co * CIN + ci + 1) * K2_ + k2];
        d_Bf[i] = pack16(v0, v1);
    }
}

// ---------------------------------------------------------------------------
// GEMM kernel: R13 verbatim (best measured: 189.6us).
//   CTA: M=128 px x N=256 couts, 512 threads (16 warps: 4M x 4N, warp 32x64).
//   64-ci chunks, fp16 coalesced gather (full-line corners), double buffered.
// ---------------------------------------------------------------------------
__global__ __launch_bounds__(512, 1)
void gemm_kernel(float* __restrict__ out) {
    extern __shared__ uint4 smem4[];
    char* smem = (char*)smem4;
    const unsigned smem_b = (unsigned)__cvta_generic_to_shared(smem);

    const int tid  = threadIdx.x;
    const int lane = tid & 31;
    const int wid  = tid >> 5;
    const int b    = blockIdx.x >> 5;
    const int l0   = (blockIdx.x & 31) << 7;   // 128-pixel tiles
    const int q    = tid & 7;                  // ci octet within 64-chunk
    const int pxh  = tid >> 3;                 // pixel (0..63); also handles +64

    // --- producer A STS offsets (validated granule layout, per-sub skew) ---
    const int r  = pxh & 15, mt = pxh >> 4;
    const int rs = (r >> 1) & 3;
    const int sub = q >> 1;
    const int wordoff = (2 * (q & 1) + (r >= 8)) * 4;
    int sa[4];
#pragma unroll
    for (int j = 0; j < 4; ++j)
        sa[j] = sub * 4112
              + (mt * 32 + ((((r & 7) << 2) | j) ^ rs)) * 16 + wordoff;

    // --- consumer fragment bases ---
    const int mtc0 = (wid & 3) * 2;
    const int ca0  = (mtc0 * 32 + (lane ^ ((lane >> 3) & 3))) * 16;
    const int bo0  = (wid >> 2) * 2048 + lane * 8;

    float acc[2][8][4];
#pragma unroll
    for (int i = 0; i < 2; ++i)
#pragma unroll
        for (int t = 0; t < 8; ++t)
#pragma unroll
            for (int w0 = 0; w0 < 4; ++w0) acc[i][t][w0] = 0.0f;

    const __half* xTb = d_xT + (size_t)b * L_ * CIN;
    int4 mia, mib; float4 mwa, mwb;
    {
        int mx = (b * K2_) * L_ + l0 + pxh;
        mia = d_mi[mx];      mwa = d_mw[mx];
        mib = d_mi[mx + 64]; mwb = d_mw[mx + 64];
    }

    // ---- prologue: chunk 0 -> buffer 0 ----
    {
#pragma unroll
        for (int i = 0; i < 4; ++i)
            cp16(smem_b + ABUF + (tid + i * 512) * 16,
                 d_Bf + (tid + i * 512) * 4);
        CP_COMMIT();

        const __half* basep = xTb + 8 * q;
        uint4 a0 = __ldg((const uint4*)(basep + (size_t)mia.x * 256));
        uint4 a1 = __ldg((const uint4*)(basep + (size_t)mia.y * 256));
        uint4 a2 = __ldg((const uint4*)(basep + (size_t)mia.z * 256));
        uint4 a3 = __ldg((const uint4*)(basep + (size_t)mia.w * 256));
        uint4 c0 = __ldg((const uint4*)(basep + (size_t)mib.x * 256));
        uint4 c1 = __ldg((const uint4*)(basep + (size_t)mib.y * 256));
        uint4 c2 = __ldg((const uint4*)(basep + (size_t)mib.z * 256));
        uint4 c3 = __ldg((const uint4*)(basep + (size_t)mib.w * 256));
        unsigned oA[4], oC[4];
        blend4(a0, a1, a2, a3, mwa, oA);
        blend4(c0, c1, c2, c3, mwb, oC);
#pragma unroll
        for (int j = 0; j < 4; ++j) {
            *(unsigned*)(smem + sa[j])        = oA[j];
            *(unsigned*)(smem + sa[j] + 2048) = oC[j];
        }
        CP_WAIT0();
    }
    __syncthreads();

    for (int ch = 0; ch < NCH; ++ch) {
        const int base  = (ch & 1) * BUF_BYTES;
        const int nbase = ((ch & 1) ^ 1) * BUF_BYTES;
        const bool more = (ch + 1) < NCH;
        uint4 a0, a1, a2, a3, c0, c1, c2, c3;

        if (more) {
            const int nc = ch + 1;
            if ((nc & 3) == 0) {
                int mx = (b * K2_ + (nc >> 2)) * L_ + l0 + pxh;
                mia = d_mi[mx];      mwa = d_mw[mx];
                mib = d_mi[mx + 64]; mwb = d_mw[mx + 64];
            }
            const __half* basep = xTb + (nc & 3) * 64 + 8 * q;
            a0 = __ldg((const uint4*)(basep + (size_t)mia.x * 256));
            a1 = __ldg((const uint4*)(basep + (size_t)mia.y * 256));
            a2 = __ldg((const uint4*)(basep + (size_t)mia.z * 256));
            a3 = __ldg((const uint4*)(basep + (size_t)mia.w * 256));
            c0 = __ldg((const uint4*)(basep + (size_t)mib.x * 256));
            c1 = __ldg((const uint4*)(basep + (size_t)mib.y * 256));
            c2 = __ldg((const uint4*)(basep + (size_t)mib.z * 256));
            c3 = __ldg((const uint4*)(basep + (size_t)mib.w * 256));
            const unsigned dstB = smem_b + nbase + ABUF;
            const unsigned* srcB = d_Bf + nc * 8192;
#pragma unroll
            for (int i = 0; i < 4; ++i)
                cp16(dstB + (tid + i * 512) * 16, srcB + (tid + i * 512) * 4);
            CP_COMMIT();
        }

        // ---- math: 4 x 16-ci subs ----
        {
            char* Ab = smem + base;
            char* Bb = smem + base + ABUF;
#pragma unroll
            for (int s = 0; s < 4; ++s) {
                const char* Ar = Ab + s * 4112;
                const char* Br = Bb + s * 8192;
                uint4 ah0 = *(const uint4*)(Ar + ca0);
                uint4 ah1 = *(const uint4*)(Ar + ca0 + 512);
                uint2 bfr[8];
#pragma unroll
                for (int t = 0; t < 8; ++t)
                    bfr[t] = *(const uint2*)(Br + bo0 + t * 256);
#pragma unroll
                for (int t = 0; t < 8; ++t) {
                    mma_fp16(acc[0][t], (const unsigned*)&ah0,
                             (const unsigned*)&bfr[t]);
                    mma_fp16(acc[1][t], (const unsigned*)&ah1,
                             (const unsigned*)&bfr[t]);
                }
            }
        }

        if (more) {
            unsigned oA[4], oC[4];
            blend4(a0, a1, a2, a3, mwa, oA);
            blend4(c0, c1, c2, c3, mwb, oC);
            char* An = smem + nbase;
#pragma unroll
            for (int j = 0; j < 4; ++j) {
                *(unsigned*)(An + sa[j])        = oA[j];
                *(unsigned*)(An + sa[j] + 2048) = oC[j];
            }
        }
        CP_WAIT0();
        __syncthreads();
    }

    // ---- epilogue: relu + direct stores (validated) ----
#pragma unroll
    for (int i = 0; i < 2; ++i) {
        int pxg = l0 + (mtc0 + i) * 16 + (lane >> 2);
#pragma unroll
        for (int t = 0; t < 8; ++t) {
            int co = (wid >> 2) * 64 + t * 8 + 2 * (lane & 3);
            float* o0 = out + ((size_t)(b * COUT + co)) * L_ + pxg;
            float* o1 = o0 + L_;
            o0[0] = fmaxf(acc[i][t][0], 0.0f);
            o1[0] = fmaxf(acc[i][t][1], 0.0f);
            o0[8] = fmaxf(acc[i][t][2], 0.0f);
            o1[8] = fmaxf(acc[i][t][3], 0.0f);
        }
    }
}

// ---------------------------------------------------------------------------
extern "C" void kernel_launch(void* const* d_in, const int* in_sizes, int n_in,
                              void* d_out, int out_size) {
    const float* x   = (const float*)d_in[0];  // [8,256,64,64]
    const float* anc = (const float*)d_in[1];  // [8,4096,5]
    const float* w   = (const float*)d_in[2];  // [256,256,3,3]
    float* out = (float*)d_out;                // [8,256,64,64]

    static int configured = 0;
    if (!configured) {
        cudaFuncSetAttribute(gemm_kernel,
                             cudaFuncAttributeMaxDynamicSharedMemorySize,
                             SMEM_BYTES);
        configured = 1;
    }

    prep_kernel<<<TR_BLOCKS + META_BLOCKS + BF_BLOCKS, 256>>>(x, anc, w);
    gemm_kernel<<<256, 512, SMEM_BYTES>>>(out);
}

// round 17
// speedup vs baseline: 1.6446x; 1.1533x over previous
#include <cuda_runtime.h>
#include <cuda_fp16.h>

#define B_    8
#define CIN   256
#define COUT  256
#define H_    64
#define W_    64
#define L_    4096
#define K2_   9
#define NCH16 144        // 9 k2 * 16 ci-chunks of 16 (B-bake granularity)
#define NCH   36         // 9 k2 * 4  ci-chunks of 64 (GEMM granularity)

#define ABUF  16512      // A region: 4 subs * 4112 (+pad)
#define BUF_BYTES (ABUF + 32768)
#define SMEM_BYTES (2 * BUF_BYTES)

// prep kernel block ranges
#define TR_BLOCKS   8192
#define META_BLOCKS 1152
#define BF_BLOCKS   1152

// Scratch (static __device__ arrays — no runtime allocation)
__device__ int4     d_mi[B_ * K2_ * L_];     // bilinear corner indices [b][k2][l]
__device__ float4   d_mw[B_ * K2_ * L_];     // bilinear corner weights (masked)
__device__ unsigned d_Bf[NCH16 * 2048];      // fp16 B frags [chunk16][tile][lane][reg]
__device__ __half   d_xT[(size_t)B_ * L_ * CIN];  // x transposed, fp16 [b][pixel][ci]

// ---------------------------------------------------------------------------
__device__ __forceinline__ void mma_fp16(float* d, const unsigned* a,
                                         const unsigned* b) {
    asm volatile(
        "mma.sync.aligned.m16n8k16.row.col.f32.f16.f16.f32 "
        "{%0,%1,%2,%3}, {%4,%5,%6,%7}, {%8,%9}, {%0,%1,%2,%3};"
        : "+f"(d[0]), "+f"(d[1]), "+f"(d[2]), "+f"(d[3])
        : "r"(a[0]), "r"(a[1]), "r"(a[2]), "r"(a[3]), "r"(b[0]), "r"(b[1]));
}
__device__ __forceinline__ void cp16(unsigned dst, const void* src) {
    asm volatile("cp.async.cg.shared.global [%0], [%1], 16;"
                 :: "r"(dst), "l"(src));
}
#define CP_COMMIT() asm volatile("cp.async.commit_group;" ::: "memory")
#define CP_WAIT0()  asm volatile("cp.async.wait_group 0;" ::: "memory")

__device__ __forceinline__ unsigned pack16(float v0, float v1) {
    __half2 h = __floats2half2_rn(v0, v1);
    return *(unsigned*)&h;
}
__device__ __forceinline__ unsigned h2b(float f) {
    __half2 h = __float2half2_rn(f);
    return *(unsigned*)&h;
}

// pure-half2 bilinear blend: 4 HFMA2 per output word, zero conversions
__device__ __forceinline__ void blend4_h2(const uint4& g0, const uint4& g1,
                                          const uint4& g2, const uint4& g3,
                                          const unsigned* w4, unsigned* o) {
    const __half2* h0 = (const __half2*)&g0;
    const __half2* h1 = (const __half2*)&g1;
    const __half2* h2 = (const __half2*)&g2;
    const __half2* h3 = (const __half2*)&g3;
    const __half2* w  = (const __half2*)w4;
#pragma unroll
    for (int j = 0; j < 4; ++j) {
        __half2 a = __hmul2(w[0], h0[j]);
        a = __hfma2(w[1], h1[j], a);
        a = __hfma2(w[2], h2[j], a);
        a = __hfma2(w[3], h3[j], a);
        o[j] = *(const unsigned*)&a;
    }
}

// ---------------------------------------------------------------------------
// Fused prep kernel (validated R16): transpose fp16 NHWC | metadata | B bake
// ---------------------------------------------------------------------------
__global__ void prep_kernel(const float* __restrict__ x,
                            const float* __restrict__ anc,
                            const float* __restrict__ w) {
    __shared__ float t[32][33];
    const int bx = blockIdx.x;

    if (bx < TR_BLOCKS) {
        const int tx = threadIdx.x & 31, ty = threadIdx.x >> 5;
        const int l0 = (bx & 127) << 5;
        const int c0 = ((bx >> 7) & 7) << 5;
        const int b  = bx >> 10;
        const float* xb = x + ((size_t)b * CIN + c0) * L_ + l0;
#pragma unroll
        for (int i = 0; i < 4; ++i)
            t[ty + i * 8][tx] = xb[(size_t)(ty + i * 8) * L_ + tx];
        __syncthreads();
        __half* ob = d_xT + ((size_t)b * L_ + l0) * CIN + c0;
#pragma unroll
        for (int i = 0; i < 4; ++i)
            ob[(size_t)(ty + i * 8) * CIN + tx] =
                __float2half_rn(t[tx][ty + i * 8]);
        return;
    }

    if (bx < TR_BLOCKS + META_BLOCKS) {
        int g = (bx - TR_BLOCKS) * 256 + threadIdx.x;
        if (g >= B_ * K2_ * L_) return;
        int l = g % L_, k2 = (g / L_) % K2_, b = g / (L_ * K2_);

        const float* a = anc + (size_t)(b * L_ + l) * 5;
        float xc = a[0] * 0.125f, yc = a[1] * 0.125f;
        float dw = (a[2] * 0.125f) / 3.0f, dh = (a[3] * 0.125f) / 3.0f;
        float s, c;
        sincosf(a[4], &s, &c);
        float fx = (float)(k2 % 3) - 1.0f, fy = (float)(k2 / 3) - 1.0f;
        float xk = dw * fx, yk = dh * fy;
        float px = (c * xk - s * yk) + xc;
        float py = (s * xk + c * yk) + yc;

        float x0f = floorf(px), y0f = floorf(py);
        int x0 = (int)x0f, y0 = (int)y0f;
        float wx1 = px - x0f, wy1 = py - y0f;
        float wx0 = 1.0f - wx1, wy0 = 1.0f - wy1;
        int x1 = x0 + 1, y1 = y0 + 1;
        float vx0 = (x0 >= 0 && x0 < W_) ? 1.f : 0.f;
        float vx1 = (x1 >= 0 && x1 < W_) ? 1.f : 0.f;
        float vy0 = (y0 >= 0 && y0 < H_) ? 1.f : 0.f;
        float vy1 = (y1 >= 0 && y1 < H_) ? 1.f : 0.f;
        int xc0 = min(max(x0, 0), W_ - 1), xc1 = min(max(x1, 0), W_ - 1);
        int yc0 = min(max(y0, 0), H_ - 1), yc1 = min(max(y1, 0), H_ - 1);
        d_mi[g] = make_int4(yc0 * W_ + xc0, yc0 * W_ + xc1,
                            yc1 * W_ + xc0, yc1 * W_ + xc1);
        d_mw[g] = make_float4(wy0 * wx0 * vy0 * vx0, wy0 * wx1 * vy0 * vx1,
                              wy1 * wx0 * vy1 * vx0, wy1 * wx1 * vy1 * vx1);
        return;
    }

    {
        int i = (bx - TR_BLOCKS - META_BLOCKS) * 256 + threadIdx.x;
        if (i >= NCH16 * 2048) return;
        int chunk = i >> 11;
        int r2    = i & 2047;
        int tile  = r2 >> 6;
        int lane  = (r2 >> 1) & 31;
        int reg   = r2 & 1;

        int co = tile * 8 + (lane >> 2);
        int kb = 2 * (lane & 3) + 8 * reg;
        int ci = (chunk & 15) * 16 + kb;
        int k2 = chunk >> 4;

        float v0 = w[((size_t)co * CIN + ci) * K2_ + k2];
        float v1 = w[((size_t)co * CIN + ci + 1) * K2_ + k2];
        d_Bf[i] = pack16(v0, v1);
    }
}

// ---------------------------------------------------------------------------
// GEMM kernel: R13/R16 topology; producer blend now pure half2 (HFMA2).
//   CTA: M=128 px x N=256 couts, 512 threads (16 warps: 4M x 4N, warp 32x64).
// ---------------------------------------------------------------------------
__global__ __launch_bounds__(512, 1)
void gemm_kernel(float* __restrict__ out) {
    extern __shared__ uint4 smem4[];
    char* smem = (char*)smem4;
    const unsigned smem_b = (unsigned)__cvta_generic_to_shared(smem);

    const int tid  = threadIdx.x;
    const int lane = tid & 31;
    const int wid  = tid >> 5;
    const int b    = blockIdx.x >> 5;
    const int l0   = (blockIdx.x & 31) << 7;   // 128-pixel tiles
    const int q    = tid & 7;                  // ci octet within 64-chunk
    const int pxh  = tid >> 3;                 // pixel (0..63); also handles +64

    // --- producer A STS offsets (validated granule layout, per-sub skew) ---
    const int r  = pxh & 15, mt = pxh >> 4;
    const int rs = (r >> 1) & 3;
    const int sub = q >> 1;
    const int wordoff = (2 * (q & 1) + (r >= 8)) * 4;
    int sa[4];
#pragma unroll
    for (int j = 0; j < 4; ++j)
        sa[j] = sub * 4112
              + (mt * 32 + ((((r & 7) << 2) | j) ^ rs)) * 16 + wordoff;

    // --- consumer fragment bases ---
    const int mtc0 = (wid & 3) * 2;
    const int ca0  = (mtc0 * 32 + (lane ^ ((lane >> 3) & 3))) * 16;
    const int bo0  = (wid >> 2) * 2048 + lane * 8;

    float acc[2][8][4];
#pragma unroll
    for (int i = 0; i < 2; ++i)
#pragma unroll
        for (int t = 0; t < 8; ++t)
#pragma unroll
            for (int w0 = 0; w0 < 4; ++w0) acc[i][t][w0] = 0.0f;

    const __half* xTb = d_xT + (size_t)b * L_ * CIN;
    int4 mia, mib;
    unsigned wa[4], wb[4];                     // half2-broadcast weights
    {
        int mx = (b * K2_) * L_ + l0 + pxh;
        mia = d_mi[mx];
        mib = d_mi[mx + 64];
        float4 fa = d_mw[mx], fb = d_mw[mx + 64];
        wa[0] = h2b(fa.x); wa[1] = h2b(fa.y); wa[2] = h2b(fa.z); wa[3] = h2b(fa.w);
        wb[0] = h2b(fb.x); wb[1] = h2b(fb.y); wb[2] = h2b(fb.z); wb[3] = h2b(fb.w);
    }

    // ---- prologue: chunk 0 -> buffer 0 ----
    {
#pragma unroll
        for (int i = 0; i < 4; ++i)
            cp16(smem_b + ABUF + (tid + i * 512) * 16,
                 d_Bf + (tid + i * 512) * 4);
        CP_COMMIT();

        const __half* basep = xTb + 8 * q;
        uint4 a0 = __ldg((const uint4*)(basep + (size_t)mia.x * 256));
        uint4 a1 = __ldg((const uint4*)(basep + (size_t)mia.y * 256));
        uint4 a2 = __ldg((const uint4*)(basep + (size_t)mia.z * 256));
        uint4 a3 = __ldg((const uint4*)(basep + (size_t)mia.w * 256));
        uint4 c0 = __ldg((const uint4*)(basep + (size_t)mib.x * 256));
        uint4 c1 = __ldg((const uint4*)(basep + (size_t)mib.y * 256));
        uint4 c2 = __ldg((const uint4*)(basep + (size_t)mib.z * 256));
        uint4 c3 = __ldg((const uint4*)(basep + (size_t)mib.w * 256));
        unsigned oA[4], oC[4];
        blend4_h2(a0, a1, a2, a3, wa, oA);
        blend4_h2(c0, c1, c2, c3, wb, oC);
#pragma unroll
        for (int j = 0; j < 4; ++j) {
            *(unsigned*)(smem + sa[j])        = oA[j];
            *(unsigned*)(smem + sa[j] + 2048) = oC[j];
        }
        CP_WAIT0();
    }
    __syncthreads();

    for (int ch = 0; ch < NCH; ++ch) {
        const int base  = (ch & 1) * BUF_BYTES;
        const int nbase = ((ch & 1) ^ 1) * BUF_BYTES;
        const bool more = (ch + 1) < NCH;
        uint4 a0, a1, a2, a3, c0, c1, c2, c3;

        if (more) {
            const int nc = ch + 1;
            if ((nc & 3) == 0) {
                int mx = (b * K2_ + (nc >> 2)) * L_ + l0 + pxh;
                mia = d_mi[mx];
                mib = d_mi[mx + 64];
                float4 fa = d_mw[mx], fb = d_mw[mx + 64];
                wa[0] = h2b(fa.x); wa[1] = h2b(fa.y);
                wa[2] = h2b(fa.z); wa[3] = h2b(fa.w);
                wb[0] = h2b(fb.x); wb[1] = h2b(fb.y);
                wb[2] = h2b(fb.z); wb[3] = h2b(fb.w);
            }
            const __half* basep = xTb + (nc & 3) * 64 + 8 * q;
            a0 = __ldg((const uint4*)(basep + (size_t)mia.x * 256));
            a1 = __ldg((const uint4*)(basep + (size_t)mia.y * 256));
            a2 = __ldg((const uint4*)(basep + (size_t)mia.z * 256));
            a3 = __ldg((const uint4*)(basep + (size_t)mia.w * 256));
            c0 = __ldg((const uint4*)(basep + (size_t)mib.x * 256));
            c1 = __ldg((const uint4*)(basep + (size_t)mib.y * 256));
            c2 = __ldg((const uint4*)(basep + (size_t)mib.z * 256));
            c3 = __ldg((const uint4*)(basep + (size_t)mib.w * 256));
            const unsigned dstB = smem_b + nbase + ABUF;
            const unsigned* srcB = d_Bf + nc * 8192;
#pragma unroll
            for (int i = 0; i < 4; ++i)
                cp16(dstB + (tid + i * 512) * 16, srcB + (tid + i * 512) * 4);
            CP_COMMIT();
        }

        // ---- math: 4 x 16-ci subs (validated R13 datapath) ----
        {
            char* Ab = smem + base;
            char* Bb = smem + base + ABUF;
#pragma unroll
            for (int s = 0; s < 4; ++s) {
                const char* Ar = Ab + s * 4112;
                const char* Br = Bb + s * 8192;
                uint4 ah0 = *(const uint4*)(Ar + ca0);
                uint4 ah1 = *(const uint4*)(Ar + ca0 + 512);
                uint2 bfr[8];
#pragma unroll
                for (int t = 0; t < 8; ++t)
                    bfr[t] = *(const uint2*)(Br + bo0 + t * 256);
#pragma unroll
                for (int t = 0; t < 8; ++t) {
                    mma_fp16(acc[0][t], (const unsigned*)&ah0,
                             (const unsigned*)&bfr[t]);
                    mma_fp16(acc[1][t], (const unsigned*)&ah1,
                             (const unsigned*)&bfr[t]);
                }
            }
        }

        if (more) {
            unsigned oA[4], oC[4];
            blend4_h2(a0, a1, a2, a3, wa, oA);
            blend4_h2(c0, c1, c2, c3, wb, oC);
            char* An = smem + nbase;
#pragma unroll
            for (int j = 0; j < 4; ++j) {
                *(unsigned*)(An + sa[j])        = oA[j];
                *(unsigned*)(An + sa[j] + 2048) = oC[j];
            }
        }
        CP_WAIT0();
        __syncthreads();
    }

    // ---- epilogue: relu + direct stores (validated) ----
#pragma unroll
    for (int i = 0; i < 2; ++i) {
        int pxg = l0 + (mtc0 + i) * 16 + (lane >> 2);
#pragma unroll
        for (int t = 0; t < 8; ++t) {
            int co = (wid >> 2) * 64 + t * 8 + 2 * (lane & 3);
            float* o0 = out + ((size_t)(b * COUT + co)) * L_ + pxg;
            float* o1 = o0 + L_;
            o0[0] = fmaxf(acc[i][t][0], 0.0f);
            o1[0] = fmaxf(acc[i][t][1], 0.0f);
            o0[8] = fmaxf(acc[i][t][2], 0.0f);
            o1[8] = fmaxf(acc[i][t][3], 0.0f);
        }
    }
}

// ---------------------------------------------------------------------------
extern "C" void kernel_launch(void* const* d_in, const int* in_sizes, int n_in,
                              void* d_out, int out_size) {
    const float* x   = (const float*)d_in[0];  // [8,256,64,64]
    const float* anc = (const float*)d_in[1];  // [8,4096,5]
    const float* w   = (const float*)d_in[2];  // [256,256,3,3]
    float* out = (float*)d_out;                // [8,256,64,64]

    static int configured = 0;
    if (!configured) {
        cudaFuncSetAttribute(gemm_kernel,
                             cudaFuncAttributeMaxDynamicSharedMemorySize,
                             SMEM_BYTES);
        configured = 1;
    }

    prep_kernel<<<TR_BLOCKS + META_BLOCKS + BF_BLOCKS, 256>>>(x, anc, w);
    gemm_kernel<<<256, 512, SMEM_BYTES>>>(out);
}